// round 2
// baseline (speedup 1.0000x reference)
#include <cuda_runtime.h>

#define NPTS 131072
#define KNBR 27
#define FINC 3
#define FOUTC 32
#define EPSV 1e-5f

// scratch for intermediate h [N, 32]  (16 MB, static — allocation rules)
__device__ float g_h[(size_t)NPTS * FOUTC];

// ---------------------------------------------------------------------------
// Stage 1: h[n,o] = silu(bn( sum_{k,f} x[nbr[n,k],f] * w1[k,f,o] ))
// thread-per-point, w1 + idx staged in smem
// ---------------------------------------------------------------------------
#define A_THREADS 256

__global__ void __launch_bounds__(A_THREADS) stage1_kernel(
    const float* __restrict__ x_feats,
    const int*   __restrict__ nbr_idx,
    const float* __restrict__ w1,
    const float* __restrict__ g1,   // gamma
    const float* __restrict__ b1,   // beta
    const float* __restrict__ m1,   // mean
    const float* __restrict__ v1)   // var
{
    __shared__ float w1s[KNBR * FINC * FOUTC];   // 2592 floats
    __shared__ int   sIdx[A_THREADS * KNBR];     // 6912 ints
    __shared__ float sScale[FOUTC], sShift[FOUTC];

    const int tid  = threadIdx.x;
    const int base = blockIdx.x * A_THREADS;

    for (int i = tid; i < KNBR * FINC * FOUTC; i += A_THREADS) w1s[i] = w1[i];
    for (int i = tid; i < A_THREADS * KNBR; i += A_THREADS)
        sIdx[i] = nbr_idx[(size_t)base * KNBR + i];
    if (tid < FOUTC) {
        float s = rsqrtf(v1[tid] + EPSV) * g1[tid];
        sScale[tid] = s;
        sShift[tid] = b1[tid] - m1[tid] * s;
    }
    __syncthreads();

    const int n = base + tid;

    float acc[FOUTC];
#pragma unroll
    for (int o = 0; o < FOUTC; o++) acc[o] = 0.f;

    for (int k = 0; k < KNBR; k++) {
        int idx = sIdx[tid * KNBR + k];
        float x0 = __ldg(x_feats + (size_t)idx * 3 + 0);
        float x1 = __ldg(x_feats + (size_t)idx * 3 + 1);
        float x2 = __ldg(x_feats + (size_t)idx * 3 + 2);
        const float4* w0 = (const float4*)&w1s[(k * 3 + 0) * FOUTC];
        const float4* w1r = (const float4*)&w1s[(k * 3 + 1) * FOUTC];
        const float4* w2r = (const float4*)&w1s[(k * 3 + 2) * FOUTC];
#pragma unroll
        for (int o4 = 0; o4 < 8; o4++) {
            float4 a = w0[o4], b = w1r[o4], c = w2r[o4];
            acc[o4 * 4 + 0] += x0 * a.x + x1 * b.x + x2 * c.x;
            acc[o4 * 4 + 1] += x0 * a.y + x1 * b.y + x2 * c.y;
            acc[o4 * 4 + 2] += x0 * a.z + x1 * b.z + x2 * c.z;
            acc[o4 * 4 + 3] += x0 * a.w + x1 * b.w + x2 * c.w;
        }
    }

    float4* hp = (float4*)(g_h + (size_t)n * FOUTC);
#pragma unroll
    for (int o4 = 0; o4 < 8; o4++) {
        float r[4];
#pragma unroll
        for (int j = 0; j < 4; j++) {
            int o = o4 * 4 + j;
            float v = acc[o] * sScale[o] + sShift[o];
            float sig = 1.f / (1.f + __expf(-v));
            r[j] = v * sig;
        }
        hp[o4] = make_float4(r[0], r[1], r[2], r[3]);
    }
}

// ---------------------------------------------------------------------------
// Stage 2: x_out[n,o] = sum_{k,f} h[nbr[n,k],f] * w2[k,f,o]
//          fused = x_out + relu(bn(z @ mlp_w + mlp_b)); out = [fused; fused]
// block tile: 128 points x 32 outs, 256 threads, thread tile 4x4, k-chunked
// ---------------------------------------------------------------------------
#define B_THREADS 256
#define TILE_P    128

__global__ void __launch_bounds__(B_THREADS) stage2_kernel(
    const float* __restrict__ z_feats,
    const int*   __restrict__ nbr_idx,
    const float* __restrict__ w2,
    const float* __restrict__ mlp_w,
    const float* __restrict__ mlp_b,
    const float* __restrict__ mg,
    const float* __restrict__ mbt,
    const float* __restrict__ mm,
    const float* __restrict__ mv,
    float* __restrict__ out)
{
    __shared__ float sA[FOUTC * TILE_P];    // [f][pt]  16 KB
    __shared__ float sB[FOUTC * FOUTC];     // [f][o]    4 KB
    __shared__ int   sIdx[TILE_P * KNBR];   // 13.5 KB

    const int tid  = threadIdx.x;
    const int base = blockIdx.x * TILE_P;

    for (int i = tid; i < TILE_P * KNBR; i += B_THREADS)
        sIdx[i] = nbr_idx[(size_t)base * KNBR + i];

    const int pg = tid & 31;   // point group (4 points)
    const int og = tid >> 5;   // output group (4 outs)

    float acc[4][4];
#pragma unroll
    for (int p = 0; p < 4; p++)
#pragma unroll
        for (int j = 0; j < 4; j++) acc[p][j] = 0.f;

    __syncthreads();

    for (int k = 0; k < KNBR; k++) {
        // ---- gather A chunk: sA[f][pt] = h[nbr[base+pt][k]][f]
#pragma unroll
        for (int c = 0; c < 4; c++) {
            int lin = tid + c * B_THREADS;
            int pt  = lin & (TILE_P - 1);
            int fc  = lin >> 7;            // 0..7 (float4 chunk within row)
            int idx = sIdx[pt * KNBR + k];
            float4 v = __ldg((const float4*)(g_h + (size_t)idx * FOUTC) + fc);
            sA[(fc * 4 + 0) * TILE_P + pt] = v.x;
            sA[(fc * 4 + 1) * TILE_P + pt] = v.y;
            sA[(fc * 4 + 2) * TILE_P + pt] = v.z;
            sA[(fc * 4 + 3) * TILE_P + pt] = v.w;
        }
        // ---- B chunk: w2[k] (32x32), 256 threads x 1 float4
        {
            float4 wv = __ldg((const float4*)(w2 + (size_t)k * FOUTC * FOUTC) + tid);
            ((float4*)sB)[tid] = wv;
        }
        __syncthreads();

        const float4* aBase = (const float4*)sA;   // f*32 + pg
        const float4* bBase = (const float4*)sB;   // f*8  + og
#pragma unroll
        for (int f = 0; f < FOUTC; f++) {
            float4 a = aBase[f * 32 + pg];
            float4 b = bBase[f * 8 + og];
            acc[0][0] += a.x * b.x; acc[0][1] += a.x * b.y;
            acc[0][2] += a.x * b.z; acc[0][3] += a.x * b.w;
            acc[1][0] += a.y * b.x; acc[1][1] += a.y * b.y;
            acc[1][2] += a.y * b.z; acc[1][3] += a.y * b.w;
            acc[2][0] += a.z * b.x; acc[2][1] += a.z * b.y;
            acc[2][2] += a.z * b.z; acc[2][3] += a.z * b.w;
            acc[3][0] += a.w * b.x; acc[3][1] += a.w * b.y;
            acc[3][2] += a.w * b.z; acc[3][3] += a.w * b.w;
        }
        __syncthreads();
    }

    // ---- epilogue: point branch + fuse + duplicated write
    float zs[4], zsh[4], w0[4], w1c[4], w2c[4], bb[4];
#pragma unroll
    for (int j = 0; j < 4; j++) {
        int o = og * 4 + j;
        float s = rsqrtf(mv[o] + EPSV) * mg[o];
        zs[j]  = s;
        zsh[j] = mbt[o] - mm[o] * s;
        w0[j]  = mlp_w[0 * FOUTC + o];
        w1c[j] = mlp_w[1 * FOUTC + o];
        w2c[j] = mlp_w[2 * FOUTC + o];
        bb[j]  = mlp_b[o];
    }

#pragma unroll
    for (int p = 0; p < 4; p++) {
        int n = base + pg * 4 + p;
        float z0 = __ldg(z_feats + (size_t)n * 3 + 0);
        float z1 = __ldg(z_feats + (size_t)n * 3 + 1);
        float z2 = __ldg(z_feats + (size_t)n * 3 + 2);
        float rv[4];
#pragma unroll
        for (int j = 0; j < 4; j++) {
            float zv = z0 * w0[j] + z1 * w1c[j] + z2 * w2c[j] + bb[j];
            zv = zv * zs[j] + zsh[j];
            zv = fmaxf(zv, 0.f);
            rv[j] = acc[p][j] + zv;
        }
        float4 r4 = make_float4(rv[0], rv[1], rv[2], rv[3]);
        *(float4*)(out + (size_t)n * FOUTC + og * 4) = r4;
        *(float4*)(out + (size_t)NPTS * FOUTC + (size_t)n * FOUTC + og * 4) = r4;
    }
}

// ---------------------------------------------------------------------------
extern "C" void kernel_launch(void* const* d_in, const int* in_sizes, int n_in,
                              void* d_out, int out_size)
{
    const float* x_feats   = (const float*)d_in[0];
    const float* z_feats   = (const float*)d_in[1];
    const int*   nbr_idx   = (const int*)  d_in[2];
    const float* w1        = (const float*)d_in[3];
    const float* bn1_gamma = (const float*)d_in[4];
    const float* bn1_beta  = (const float*)d_in[5];
    const float* bn1_mean  = (const float*)d_in[6];
    const float* bn1_var   = (const float*)d_in[7];
    const float* w2        = (const float*)d_in[8];
    const float* mlp_w     = (const float*)d_in[9];
    const float* mlp_b     = (const float*)d_in[10];
    const float* mlp_gamma = (const float*)d_in[11];
    const float* mlp_beta  = (const float*)d_in[12];
    const float* mlp_mean  = (const float*)d_in[13];
    const float* mlp_var   = (const float*)d_in[14];
    float* out = (float*)d_out;

    stage1_kernel<<<NPTS / A_THREADS, A_THREADS>>>(
        x_feats, nbr_idx, w1, bn1_gamma, bn1_beta, bn1_mean, bn1_var);

    stage2_kernel<<<NPTS / TILE_P, B_THREADS>>>(
        z_feats, nbr_idx, w2, mlp_w, mlp_b,
        mlp_gamma, mlp_beta, mlp_mean, mlp_var, out);
}

// round 3
// speedup vs baseline: 1.4156x; 1.4156x over previous
#include <cuda_runtime.h>

#define NPTS 131072
#define KNBR 27
#define FINC 3
#define FOUTC 32
#define EPSV 1e-5f

// static scratch (allocation rules forbid cudaMalloc)
__device__ float g_h[(size_t)NPTS * FOUTC];          // 16 MB intermediate h
__device__ float g_x4[(size_t)NPTS * 4];             // 2 MB padded x feats
__device__ int   g_idxT[(size_t)KNBR * NPTS];        // 14 MB transposed indices

typedef unsigned long long ull;

__device__ __forceinline__ ull pk2(float lo, float hi) {
    ull r; asm("mov.b64 %0, {%1, %2};" : "=l"(r) : "f"(lo), "f"(hi)); return r;
}
__device__ __forceinline__ void upk2(ull v, float& lo, float& hi) {
    asm("mov.b64 {%0, %1}, %2;" : "=f"(lo), "=f"(hi) : "l"(v));
}
__device__ __forceinline__ void ffma2(ull& d, ull a, ull b) {
    asm("fma.rn.f32x2 %0, %1, %2, %0;" : "+l"(d) : "l"(a), "l"(b));
}

// ---------------------------------------------------------------------------
// Pre-pass A: pack x_feats [N,3] -> g_x4 [N,4]
// ---------------------------------------------------------------------------
__global__ void __launch_bounds__(256) pack_x_kernel(const float* __restrict__ x)
{
    int n = blockIdx.x * 256 + threadIdx.x;
    if (n < NPTS) {
        float4 v;
        v.x = x[(size_t)n * 3 + 0];
        v.y = x[(size_t)n * 3 + 1];
        v.z = x[(size_t)n * 3 + 2];
        v.w = 0.f;
        ((float4*)g_x4)[n] = v;
    }
}

// ---------------------------------------------------------------------------
// Pre-pass B: transpose nbr_idx [N,K] -> g_idxT [K,N]  (smem-tiled)
// ---------------------------------------------------------------------------
__global__ void __launch_bounds__(256) transpose_idx_kernel(const int* __restrict__ nbr)
{
    __shared__ int sI[256 * KNBR];
    const int tid  = threadIdx.x;
    const int base = blockIdx.x * 256;
    for (int i = tid; i < 256 * KNBR; i += 256)
        sI[i] = nbr[(size_t)base * KNBR + i];
    __syncthreads();
#pragma unroll
    for (int k = 0; k < KNBR; k++)
        g_idxT[(size_t)k * NPTS + base + tid] = sI[tid * KNBR + k];
}

// ---------------------------------------------------------------------------
// Stage 1: h[n,o] = silu(bn( sum_{k,f} x4[idxT[k][n]].f * w1[k,f,o] ))
// thread-per-point; float4 gather from packed x
// ---------------------------------------------------------------------------
#define A_THREADS 256

__global__ void __launch_bounds__(A_THREADS) stage1_kernel(
    const float* __restrict__ w1,
    const float* __restrict__ g1,
    const float* __restrict__ b1,
    const float* __restrict__ m1,
    const float* __restrict__ v1)
{
    __shared__ float w1s[KNBR * FINC * FOUTC];
    __shared__ float sScale[FOUTC], sShift[FOUTC];

    const int tid = threadIdx.x;
    const int n   = blockIdx.x * A_THREADS + tid;

    for (int i = tid; i < KNBR * FINC * FOUTC; i += A_THREADS) w1s[i] = w1[i];
    if (tid < FOUTC) {
        float s = rsqrtf(v1[tid] + EPSV) * g1[tid];
        sScale[tid] = s;
        sShift[tid] = b1[tid] - m1[tid] * s;
    }
    __syncthreads();

    float acc[FOUTC];
#pragma unroll
    for (int o = 0; o < FOUTC; o++) acc[o] = 0.f;

    for (int k = 0; k < KNBR; k++) {
        int idx = __ldg(g_idxT + (size_t)k * NPTS + n);
        float4 xv = __ldg((const float4*)g_x4 + idx);
        const float4* w0r = (const float4*)&w1s[(k * 3 + 0) * FOUTC];
        const float4* w1r = (const float4*)&w1s[(k * 3 + 1) * FOUTC];
        const float4* w2r = (const float4*)&w1s[(k * 3 + 2) * FOUTC];
#pragma unroll
        for (int o4 = 0; o4 < 8; o4++) {
            float4 a = w0r[o4], b = w1r[o4], c = w2r[o4];
            acc[o4 * 4 + 0] += xv.x * a.x + xv.y * b.x + xv.z * c.x;
            acc[o4 * 4 + 1] += xv.x * a.y + xv.y * b.y + xv.z * c.y;
            acc[o4 * 4 + 2] += xv.x * a.z + xv.y * b.z + xv.z * c.z;
            acc[o4 * 4 + 3] += xv.x * a.w + xv.y * b.w + xv.z * c.w;
        }
    }

    float4* hp = (float4*)(g_h + (size_t)n * FOUTC);
#pragma unroll
    for (int o4 = 0; o4 < 8; o4++) {
        float r[4];
#pragma unroll
        for (int j = 0; j < 4; j++) {
            int o = o4 * 4 + j;
            float v = acc[o] * sScale[o] + sShift[o];
            float sig = 1.f / (1.f + __expf(-v));
            r[j] = v * sig;
        }
        hp[o4] = make_float4(r[0], r[1], r[2], r[3]);
    }
}

// ---------------------------------------------------------------------------
// Stage 2: x_out[n,o] = sum_{k,f} h[idxT[k][n],f] * w2[k,f,o]; fuse point branch.
// 256 pts/block, 256 threads, thread tile 4 pts x 8 outs, FFMA2 (f32x2) math.
// sA layout [f][pt] stride 257 (conflict-free for gather STS and math LDS).
// ---------------------------------------------------------------------------
#define B_THREADS 256
#define TILE_P    256
#define SASTR     257

__global__ void __launch_bounds__(B_THREADS) stage2_kernel(
    const float* __restrict__ z_feats,
    const float* __restrict__ w2,
    const float* __restrict__ mlp_w,
    const float* __restrict__ mlp_b,
    const float* __restrict__ mg,
    const float* __restrict__ mbt,
    const float* __restrict__ mm,
    const float* __restrict__ mv,
    float* __restrict__ out)
{
    __shared__ float sA[FOUTC * SASTR];   // 32.9 KB  [f][pt]
    __shared__ float sB[FOUTC * FOUTC];   // 4 KB     [f][o]

    const int tid  = threadIdx.x;
    const int lane = tid & 31;
    const int wid  = tid >> 5;
    const int og   = wid & 3;                 // out group: outs [og*8, og*8+8)
    const int pg   = ((wid >> 2) << 5) | lane; // 0..63; pts {pg + j*64}
    const int base = blockIdx.x * TILE_P;

    ull acc[4][4];   // [j: point][q: out-pair]
#pragma unroll
    for (int j = 0; j < 4; j++)
#pragma unroll
        for (int q = 0; q < 4; q++) acc[j][q] = 0ULL;

    for (int k = 0; k < KNBR; k++) {
        __syncthreads();   // protect sA/sB from previous iteration's readers

        // ---- gather: 8 lanes per point -> 4 cache lines per warp
        const int* __restrict__ idxk = g_idxT + (size_t)k * NPTS + base;
#pragma unroll
        for (int pass = 0; pass < 8; pass++) {
            int lin = pass * B_THREADS + tid;
            int pt  = lin >> 3;          // 0..255
            int fc  = lin & 7;           // float4 chunk 0..7
            int idx = __ldg(idxk + pt);
            float4 v = __ldg((const float4*)(g_h + (size_t)idx * FOUTC) + fc);
            int f0 = fc * 4;
            sA[(f0 + 0) * SASTR + pt] = v.x;
            sA[(f0 + 1) * SASTR + pt] = v.y;
            sA[(f0 + 2) * SASTR + pt] = v.z;
            sA[(f0 + 3) * SASTR + pt] = v.w;
        }
        // ---- stage w2[k] (32x32): 256 threads x 1 float4
        ((float4*)sB)[tid] = __ldg((const float4*)(w2 + (size_t)k * FOUTC * FOUTC) + tid);
        __syncthreads();

        // ---- math: 4 pts x 8 outs, out-pairs in f32x2
        const float* aCol = sA + pg;
#pragma unroll
        for (int f = 0; f < FOUTC; f++) {
            float a0 = aCol[f * SASTR +   0];
            float a1 = aCol[f * SASTR +  64];
            float a2 = aCol[f * SASTR + 128];
            float a3 = aCol[f * SASTR + 192];
            ull pa0 = pk2(a0, a0);
            ull pa1 = pk2(a1, a1);
            ull pa2 = pk2(a2, a2);
            ull pa3 = pk2(a3, a3);
            const ull* bp = (const ull*)(sB + f * FOUTC + og * 8);  // broadcast
            ull b0 = bp[0], b1 = bp[1], b2 = bp[2], b3 = bp[3];
            ffma2(acc[0][0], pa0, b0); ffma2(acc[0][1], pa0, b1);
            ffma2(acc[0][2], pa0, b2); ffma2(acc[0][3], pa0, b3);
            ffma2(acc[1][0], pa1, b0); ffma2(acc[1][1], pa1, b1);
            ffma2(acc[1][2], pa1, b2); ffma2(acc[1][3], pa1, b3);
            ffma2(acc[2][0], pa2, b0); ffma2(acc[2][1], pa2, b1);
            ffma2(acc[2][2], pa2, b2); ffma2(acc[2][3], pa2, b3);
            ffma2(acc[3][0], pa3, b0); ffma2(acc[3][1], pa3, b1);
            ffma2(acc[3][2], pa3, b2); ffma2(acc[3][3], pa3, b3);
        }
    }

    // ---- epilogue: point branch + fuse + duplicated write
    float zs[8], zsh[8], mw0[8], mw1[8], mw2[8], mbb[8];
#pragma unroll
    for (int q = 0; q < 8; q++) {
        int o = og * 8 + q;
        float s = rsqrtf(__ldg(mv + o) + EPSV) * __ldg(mg + o);
        zs[q]  = s;
        zsh[q] = __ldg(mbt + o) - __ldg(mm + o) * s;
        mw0[q] = __ldg(mlp_w + 0 * FOUTC + o);
        mw1[q] = __ldg(mlp_w + 1 * FOUTC + o);
        mw2[q] = __ldg(mlp_w + 2 * FOUTC + o);
        mbb[q] = __ldg(mlp_b + o);
    }

#pragma unroll
    for (int j = 0; j < 4; j++) {
        int n = base + pg + j * 64;
        float z0 = __ldg(z_feats + (size_t)n * 3 + 0);
        float z1 = __ldg(z_feats + (size_t)n * 3 + 1);
        float z2 = __ldg(z_feats + (size_t)n * 3 + 2);
        float rv[8];
#pragma unroll
        for (int q = 0; q < 4; q++) {
            float lo, hi;
            upk2(acc[j][q], lo, hi);
            rv[q * 2 + 0] = lo;
            rv[q * 2 + 1] = hi;
        }
#pragma unroll
        for (int q = 0; q < 8; q++) {
            float zv = z0 * mw0[q] + z1 * mw1[q] + z2 * mw2[q] + mbb[q];
            zv = zv * zs[q] + zsh[q];
            zv = fmaxf(zv, 0.f);
            rv[q] += zv;
        }
        float4 r0 = make_float4(rv[0], rv[1], rv[2], rv[3]);
        float4 r1 = make_float4(rv[4], rv[5], rv[6], rv[7]);
        float* p0 = out + (size_t)n * FOUTC + og * 8;
        float* p1 = p0 + (size_t)NPTS * FOUTC;
        ((float4*)p0)[0] = r0;
        ((float4*)p0)[1] = r1;
        ((float4*)p1)[0] = r0;
        ((float4*)p1)[1] = r1;
    }
}

// ---------------------------------------------------------------------------
extern "C" void kernel_launch(void* const* d_in, const int* in_sizes, int n_in,
                              void* d_out, int out_size)
{
    const float* x_feats   = (const float*)d_in[0];
    const float* z_feats   = (const float*)d_in[1];
    const int*   nbr_idx   = (const int*)  d_in[2];
    const float* w1        = (const float*)d_in[3];
    const float* bn1_gamma = (const float*)d_in[4];
    const float* bn1_beta  = (const float*)d_in[5];
    const float* bn1_mean  = (const float*)d_in[6];
    const float* bn1_var   = (const float*)d_in[7];
    const float* w2        = (const float*)d_in[8];
    const float* mlp_w     = (const float*)d_in[9];
    const float* mlp_b     = (const float*)d_in[10];
    const float* mlp_gamma = (const float*)d_in[11];
    const float* mlp_beta  = (const float*)d_in[12];
    const float* mlp_mean  = (const float*)d_in[13];
    const float* mlp_var   = (const float*)d_in[14];
    float* out = (float*)d_out;

    pack_x_kernel<<<(NPTS + 255) / 256, 256>>>(x_feats);
    transpose_idx_kernel<<<NPTS / 256, 256>>>(nbr_idx);

    stage1_kernel<<<NPTS / A_THREADS, A_THREADS>>>(
        w1, bn1_gamma, bn1_beta, bn1_mean, bn1_var);

    stage2_kernel<<<NPTS / TILE_P, B_THREADS>>>(
        z_feats, w2, mlp_w, mlp_b,
        mlp_gamma, mlp_beta, mlp_mean, mlp_var, out);
}